// round 1
// baseline (speedup 1.0000x reference)
#include <cuda_runtime.h>
#include <math.h>

#define NPTS 1024
#define KNB  16
#define DIM  64
#define NA   12
#define PH   64
#define AH   256
#define STR  20   // shared row stride (floats): 16B-aligned + bank-spread

// ---- scratch (device globals; no allocation allowed) ----
__device__ int   g_idx[NPTS * KNB];
__device__ float g_q[NPTS * NA * DIM];
__device__ float g_k[NPTS * NA * DIM];
__device__ float g_v[NPTS * NA * DIM];

// ===================================================================
// Kernel 1: KNN. One warp per query point. 32 distances per lane in
// registers; 16 rounds of warp argmin with (d2, idx) lexicographic
// tie-break (matches top_k stable ordering; only the SET matters
// downstream since softmax+sum over k is permutation invariant).
// ===================================================================
__global__ void knn_kernel(const float* __restrict__ xyz)
{
    int n = blockIdx.x;
    int lane = threadIdx.x;

    float px = xyz[n], py = xyz[NPTS + n], pz = xyz[2 * NPTS + n];
    float sqn = px * px + py * py + pz * pz;

    float d[32];
#pragma unroll
    for (int j = 0; j < 32; j++) {
        int m = lane + j * 32;
        float qx = xyz[m], qy = xyz[NPTS + m], qz = xyz[2 * NPTS + m];
        float sqm = qx * qx + qy * qy + qz * qz;
        d[j] = sqn + sqm - 2.0f * (px * qx + py * qy + pz * qz);
    }

    for (int t = 0; t < KNB; t++) {
        float best = 3.4e38f;
        int bidx = 1 << 30;
#pragma unroll
        for (int j = 0; j < 32; j++) {
            int m = lane + j * 32;
            if (d[j] < best || (d[j] == best && m < bidx)) { best = d[j]; bidx = m; }
        }
#pragma unroll
        for (int off = 16; off; off >>= 1) {
            float ob = __shfl_xor_sync(0xffffffffu, best, off);
            int   oi = __shfl_xor_sync(0xffffffffu, bidx, off);
            if (ob < best || (ob == best && oi < bidx)) { best = ob; bidx = oi; }
        }
        if (lane == 0) g_idx[n * KNB + t] = bidx;
        if ((bidx & 31) == lane) {
            int jj = bidx >> 5;
#pragma unroll
            for (int j = 0; j < 32; j++) if (j == jj) d[j] = 3.4e38f;
        }
    }
}

// ===================================================================
// Kernel 2: QKV projection. One block per point n, computes all 12
// anchors. Output TRANSPOSED to [n][a][c] so neighbor gathers in the
// attention kernel are contiguous 256B rows.
//   qkv[j,n,a] = sum_i to_qkv[j,i] * feats[i,n,a]
// ===================================================================
__global__ __launch_bounds__(256) void qkv_kernel(
    const float* __restrict__ feats,     // [64][1024][12]
    const float* __restrict__ to_qkv)    // [192][64]
{
    __shared__ float sf[DIM * NA];       // feats[:, n, :]
    int n = blockIdx.x;
    int t = threadIdx.x;

    for (int idx = t; idx < DIM * NA; idx += 256) {
        int i = idx / NA, a = idx % NA;
        sf[idx] = feats[(i * NPTS + n) * NA + a];
    }
    __syncthreads();

    for (int o = t; o < 3 * DIM * NA; o += 256) {
        int j = o / NA, a = o % NA;
        const float* w = to_qkv + j * DIM;
        float acc = 0.0f;
#pragma unroll 16
        for (int i = 0; i < DIM; i++) acc += w[i] * sf[i * NA + a];
        int c = j & (DIM - 1);
        float* dst = (j < DIM) ? g_q : (j < 2 * DIM ? g_k : g_v);
        dst[(n * NA + a) * DIM + c] = acc;
    }
}

// ===================================================================
// Kernel 3: fused attention. One 256-thread block per (n, a).
//  A: load idx, q; compute gx = anchors[a] @ rel  (3 x 16)
//  B: pe1 = relu(pos_mlp1 @ gx)                   (64 x 16)
//  C: pe = pos_mlp2 @ pe1; gather k,v;
//     sim = q - k_g + pe; v_g = v + pe            (64 x 16)
//  E: h = relu(attn_mlp1 @ sim)                   (256 x 16)  [dominant]
//  F: s2 = attn_mlp2 @ h                          (64 x 16)   [dominant]
//  G: softmax over k per channel; out = sum attn * v_g
// ===================================================================
__device__ __forceinline__ void fma4(float4& acc, float s, const float4 v) {
    acc.x += s * v.x; acc.y += s * v.y; acc.z += s * v.z; acc.w += s * v.w;
}

__global__ __launch_bounds__(256) void attn_kernel(
    const float* __restrict__ xyz,       // [3][1024]
    const float* __restrict__ anchors,   // [12][3][3]
    const float* __restrict__ P1,        // [64][3]
    const float* __restrict__ P2,        // [64][64]
    const float* __restrict__ W1,        // [256][64]
    const float* __restrict__ W2,        // [64][256]
    float* __restrict__ out)             // [64][1024][12]
{
    __shared__ float s_q[DIM];
    __shared__ float s_gx[3][KNB];
    __shared__ int   s_idx[KNB];
    __shared__ float s_sim[DIM * STR];   // also reused for s2 in phase F
    __shared__ float s_vg[DIM * STR];
    __shared__ float s_h[AH * STR];      // pe1 aliases the front of this
    float* s_pe1 = s_h;

    int a = blockIdx.x % NA;
    int n = blockIdx.x / NA;
    int t = threadIdx.x;

    // ---- Phase A ----
    if (t < KNB) {
        int m = g_idx[n * KNB + t];
        s_idx[t] = m;
        float rx = xyz[n]            - xyz[m];
        float ry = xyz[NPTS + n]     - xyz[NPTS + m];
        float rz = xyz[2 * NPTS + n] - xyz[2 * NPTS + m];
        const float* A = anchors + a * 9;
        s_gx[0][t] = A[0] * rx + A[1] * ry + A[2] * rz;
        s_gx[1][t] = A[3] * rx + A[4] * ry + A[5] * rz;
        s_gx[2][t] = A[6] * rx + A[7] * ry + A[8] * rz;
    }
    if (t >= 64 && t < 64 + DIM) {
        int c = t - 64;
        s_q[c] = g_q[(n * NA + a) * DIM + c];
    }
    __syncthreads();

    // ---- Phase B: pe1[j][k] = relu(P1[j,:] . gx[:,k]) ----
    {
        int j = t >> 2, kq = t & 3, k0 = kq * 4;
        float p0 = P1[j * 3 + 0], p1 = P1[j * 3 + 1], p2 = P1[j * 3 + 2];
        float4 r;
        r.x = fmaxf(p0 * s_gx[0][k0 + 0] + p1 * s_gx[1][k0 + 0] + p2 * s_gx[2][k0 + 0], 0.0f);
        r.y = fmaxf(p0 * s_gx[0][k0 + 1] + p1 * s_gx[1][k0 + 1] + p2 * s_gx[2][k0 + 1], 0.0f);
        r.z = fmaxf(p0 * s_gx[0][k0 + 2] + p1 * s_gx[1][k0 + 2] + p2 * s_gx[2][k0 + 2], 0.0f);
        r.w = fmaxf(p0 * s_gx[0][k0 + 3] + p1 * s_gx[1][k0 + 3] + p2 * s_gx[2][k0 + 3], 0.0f);
        *(float4*)&s_pe1[j * STR + k0] = r;
    }
    __syncthreads();

    // ---- Phase C: pe = P2 @ pe1 ; gather k/v ; build sim and v_g ----
    {
        int c = t >> 2, kq = t & 3, k0 = kq * 4;
        float4 pe = make_float4(0.f, 0.f, 0.f, 0.f);
        const float* P2row = P2 + c * PH;
#pragma unroll
        for (int j4 = 0; j4 < PH / 4; j4++) {
            float4 w  = *(const float4*)(P2row + j4 * 4);
            float4 v0 = *(const float4*)&s_pe1[(j4 * 4 + 0) * STR + k0];
            float4 v1 = *(const float4*)&s_pe1[(j4 * 4 + 1) * STR + k0];
            float4 v2 = *(const float4*)&s_pe1[(j4 * 4 + 2) * STR + k0];
            float4 v3 = *(const float4*)&s_pe1[(j4 * 4 + 3) * STR + k0];
            fma4(pe, w.x, v0); fma4(pe, w.y, v1); fma4(pe, w.z, v2); fma4(pe, w.w, v3);
        }
        float qc = s_q[c];
        int m0 = s_idx[k0 + 0], m1 = s_idx[k0 + 1], m2 = s_idx[k0 + 2], m3 = s_idx[k0 + 3];
        int b0 = (m0 * NA + a) * DIM + c;
        int b1 = (m1 * NA + a) * DIM + c;
        int b2 = (m2 * NA + a) * DIM + c;
        int b3 = (m3 * NA + a) * DIM + c;
        float4 sim, vg;
        sim.x = qc - g_k[b0] + pe.x;  vg.x = g_v[b0] + pe.x;
        sim.y = qc - g_k[b1] + pe.y;  vg.y = g_v[b1] + pe.y;
        sim.z = qc - g_k[b2] + pe.z;  vg.z = g_v[b2] + pe.z;
        sim.w = qc - g_k[b3] + pe.w;  vg.w = g_v[b3] + pe.w;
        *(float4*)&s_sim[c * STR + k0] = sim;
        *(float4*)&s_vg[c * STR + k0]  = vg;
    }
    __syncthreads();

    // ---- Phase E: h[r][0..15] = relu(W1[r,:] @ sim)  (16 acc / thread) ----
    {
        int r = t;
        float4 h0 = make_float4(0.f, 0.f, 0.f, 0.f);
        float4 h1 = h0, h2 = h0, h3 = h0;
        const float* W1row = W1 + r * DIM;
#pragma unroll 4
        for (int c4 = 0; c4 < DIM / 4; c4++) {
            float4 w = __ldg((const float4*)(W1row + c4 * 4));
            float wsel[4] = {w.x, w.y, w.z, w.w};
#pragma unroll
            for (int cc = 0; cc < 4; cc++) {
                int c = c4 * 4 + cc;
                float wc = wsel[cc];
                float4 sA = *(const float4*)&s_sim[c * STR + 0];
                float4 sB = *(const float4*)&s_sim[c * STR + 4];
                float4 sC = *(const float4*)&s_sim[c * STR + 8];
                float4 sD = *(const float4*)&s_sim[c * STR + 12];
                fma4(h0, wc, sA); fma4(h1, wc, sB); fma4(h2, wc, sC); fma4(h3, wc, sD);
            }
        }
        float4 o0 = make_float4(fmaxf(h0.x, 0.f), fmaxf(h0.y, 0.f), fmaxf(h0.z, 0.f), fmaxf(h0.w, 0.f));
        float4 o1 = make_float4(fmaxf(h1.x, 0.f), fmaxf(h1.y, 0.f), fmaxf(h1.z, 0.f), fmaxf(h1.w, 0.f));
        float4 o2 = make_float4(fmaxf(h2.x, 0.f), fmaxf(h2.y, 0.f), fmaxf(h2.z, 0.f), fmaxf(h2.w, 0.f));
        float4 o3 = make_float4(fmaxf(h3.x, 0.f), fmaxf(h3.y, 0.f), fmaxf(h3.z, 0.f), fmaxf(h3.w, 0.f));
        *(float4*)&s_h[r * STR + 0]  = o0;
        *(float4*)&s_h[r * STR + 4]  = o1;
        *(float4*)&s_h[r * STR + 8]  = o2;
        *(float4*)&s_h[r * STR + 12] = o3;
    }
    __syncthreads();

    // ---- Phase F: s2[c][k0..k0+3] = W2[c,:] @ h  (reuse s_sim) ----
    {
        int c = t >> 2, kq = t & 3, k0 = kq * 4;
        float4 acc = make_float4(0.f, 0.f, 0.f, 0.f);
        const float* W2row = W2 + c * AH;
#pragma unroll 8
        for (int h4 = 0; h4 < AH / 4; h4++) {
            float4 w  = __ldg((const float4*)(W2row + h4 * 4));
            float4 h0 = *(const float4*)&s_h[(h4 * 4 + 0) * STR + k0];
            float4 h1 = *(const float4*)&s_h[(h4 * 4 + 1) * STR + k0];
            float4 h2 = *(const float4*)&s_h[(h4 * 4 + 2) * STR + k0];
            float4 h3 = *(const float4*)&s_h[(h4 * 4 + 3) * STR + k0];
            fma4(acc, w.x, h0); fma4(acc, w.y, h1); fma4(acc, w.z, h2); fma4(acc, w.w, h3);
        }
        *(float4*)&s_sim[c * STR + k0] = acc;   // s2
    }
    __syncthreads();

    // ---- Phase G: per-channel softmax over k, aggregate with v_g ----
    if (t < DIM) {
        int c = t;
        float mx = -3.4e38f;
#pragma unroll
        for (int k = 0; k < KNB; k++) mx = fmaxf(mx, s_sim[c * STR + k]);
        float sum = 0.f, acc = 0.f;
#pragma unroll
        for (int k = 0; k < KNB; k++) {
            float e = expf(s_sim[c * STR + k] - mx);
            sum += e;
            acc += e * s_vg[c * STR + k];
        }
        out[(c * NPTS + n) * NA + a] = acc / sum;
    }
}

// ===================================================================
extern "C" void kernel_launch(void* const* d_in, const int* in_sizes, int n_in,
                              void* d_out, int out_size)
{
    const float* xyz       = (const float*)d_in[0];   // [1,3,1024]
    const float* feats     = (const float*)d_in[1];   // [1,64,1024,12]
    const float* anchors   = (const float*)d_in[2];   // [12,3,3]
    const float* to_qkv    = (const float*)d_in[3];   // [192,64]
    const float* pos_mlp1  = (const float*)d_in[4];   // [64,3]
    const float* pos_mlp2  = (const float*)d_in[5];   // [64,64]
    const float* attn_mlp1 = (const float*)d_in[6];   // [256,64]
    const float* attn_mlp2 = (const float*)d_in[7];   // [64,256]
    float* out = (float*)d_out;                       // [1,64,1024,12]

    knn_kernel<<<NPTS, 32>>>(xyz);
    qkv_kernel<<<NPTS, 256>>>(feats, to_qkv);
    attn_kernel<<<NPTS * NA, 256>>>(xyz, anchors, pos_mlp1, pos_mlp2,
                                    attn_mlp1, attn_mlp2, out);
}